// round 10
// baseline (speedup 1.0000x reference)
#include <cuda_runtime.h>
#include <math_constants.h>

// KNN min-dist, 9x9 window, C=3, zero-padded.
// d^2 = |t|^2 + (|o|^2 - 2 t.o), q=|o|^2 in float4.w -> 3 FFMA + 1 FMNMX/shift.
// TY=8 vertical blocking in 64-thread blocks: LDS/px 27->18, issue slots/px
// -20%, leaving the FFMA pipe as the single binding floor. dj rolled (small
// I$ body), rows fully unrolled with 2-deep register lookahead (R7 win).
// Fixed shapes: B=4, C=3, H=256, W=512.

#define BDIM 64
#define TW 32
#define TH 16
#define TY 8
#define HALO 4
#define SW 9

#define B_ 4
#define H_ 256
#define W_ 512
#define HW_ (H_*W_)

#define SH_H (TH + 2*HALO)   // 24
#define SH_W (TW + 2*HALO)   // 40
#define NR (TY + SW - 1)     // 16 rows per column pass

__global__ __launch_bounds__(BDIM, 12) void knn_min_kernel(
    const float* __restrict__ tfm, const float* __restrict__ obs,
    float* __restrict__ out)
{
    __shared__ float4 s4[SH_H][SH_W];   // (o0, o1, o2, |o|^2)

    const int b  = blockIdx.z;
    const int x0 = blockIdx.x * TW;
    const int y0 = blockIdx.y * TH;
    const int tid = threadIdx.x;
    const int tx = tid & 31;
    const int ty = tid >> 5;            // 0..1: which 8-row strip

    const float* obs_b = obs + b * 3 * HW_;
    const float* tfm_b = tfm + b * 3 * HW_;

    // ---- load obs tile (zero-padded halo), q = |o|^2 on the fly ----
    for (int idx = tid; idx < SH_H * SH_W; idx += BDIM) {
        int iy = idx / SH_W;
        int ix = idx - iy * SH_W;
        int gy = y0 - HALO + iy;
        int gx = x0 - HALO + ix;
        float v0 = 0.f, v1 = 0.f, v2 = 0.f;
        if (gy >= 0 && gy < H_ && gx >= 0 && gx < W_) {
            int g = gy * W_ + gx;
            v0 = obs_b[g];
            v1 = obs_b[HW_ + g];
            v2 = obs_b[2 * HW_ + g];
        }
        float q = fmaf(v2, v2, fmaf(v1, v1, v0 * v0));
        s4[iy][ix] = make_float4(v0, v1, v2, q);
    }
    __syncthreads();

    // ---- per-pixel constants: nt_c = -2 t_c, tt = |t|^2 (8 px/thread) ----
    const int ybase = y0 + ty * TY;
    const int xg = x0 + tx;
    float nt0[TY], nt1[TY], nt2[TY], tt[TY], m[TY];
#pragma unroll
    for (int k = 0; k < TY; k++) {
        int g = (ybase + k) * W_ + xg;
        float a = tfm_b[g];
        float c = tfm_b[HW_ + g];
        float e = tfm_b[2 * HW_ + g];
        nt0[k] = -2.f * a;
        nt1[k] = -2.f * c;
        nt2[k] = -2.f * e;
        tt[k]  = fmaf(e, e, fmaf(c, c, a * a));
        m[k] = CUDART_INF_F;
    }

    const float4* base = &s4[ty * TY][tx];

#pragma unroll 1
    for (int dj = 0; dj < SW; dj++) {
        const float4* col = base + dj;
        float4 buf[3];
        buf[0] = col[0];
        buf[1] = col[SH_W];
#pragma unroll
        for (int r = 0; r < NR; r++) {
            if (r + 2 < NR)
                buf[(r + 2) % 3] = col[(r + 2) * SH_W];
            const float4 v = buf[r % 3];
#pragma unroll
            for (int k = 0; k < TY; k++) {
                const int di = r - k;
                if (di >= 0 && di < SW) {
                    float e = fmaf(nt0[k], v.x,
                              fmaf(nt1[k], v.y,
                              fmaf(nt2[k], v.z, v.w)));
                    m[k] = fminf(m[k], e);
                }
            }
        }
    }

    float* out_b = out + b * HW_;
#pragma unroll
    for (int k = 0; k < TY; k++) {
        out_b[(ybase + k) * W_ + xg] = sqrtf(fmaxf(tt[k] + m[k], 0.f));
    }
}

extern "C" void kernel_launch(void* const* d_in, const int* in_sizes, int n_in,
                              void* d_out, int out_size)
{
    const float* tfm = (const float*)d_in[0];
    const float* obs = (const float*)d_in[1];
    float* out = (float*)d_out;
    (void)in_sizes; (void)n_in; (void)out_size;

    dim3 grid(W_ / TW, H_ / TH, B_);   // 16 x 16 x 4 = 1024 blocks
    dim3 block(BDIM);
    knn_min_kernel<<<grid, block>>>(tfm, obs, out);
}